// round 3
// baseline (speedup 1.0000x reference)
#include <cuda_runtime.h>
#include <cuda_bf16.h>
#include <cstdint>
#include <cstddef>

#define D_MODEL 512
#define HIDDEN  1408
#define TWO_H   2816
#define TILE_M  128
#define TILE_NB 256        // B rows per CTA
#define KC      64         // fp32 K elements per chunk (-> 128B bf16 rows, SW128)
#define THREADS 256

// smem layout (bytes, single buffer):
//   A_hi [128][64]bf16 @0      (16384)
//   A_lo            @16384     (16384)
//   B_hi [256][64]bf16 @32768  (32768)
//   B_lo            @65536     (32768)  -> 98304 total mainloop
// GEMM1 epilogue reuses [0,131072) as fp32 tile [128][256].
#define OFF_AH 0
#define OFF_AL 16384
#define OFF_BH 32768
#define OFF_BL 65536
#define SMEM_MAIN 98304
#define SMEM_G1   131072

// fp32 intermediate h [32768, 1408] — device-global scratch (no runtime alloc)
__device__ float g_h[32768ull * HIDDEN];

__device__ __forceinline__ uint32_t smem_u32(const void* p) {
    uint32_t a;
    asm("{ .reg .u64 t; cvta.to.shared.u64 t, %1; cvt.u32.u64 %0, t; }" : "=r"(a) : "l"(p));
    return a;
}
__device__ __forceinline__ uint32_t swz(uint32_t off) { return off ^ ((off >> 3) & 0x70); }

__device__ __forceinline__ void ldsm4(uint32_t addr, uint32_t r[4]) {
    asm volatile("ldmatrix.sync.aligned.m8n8.x4.shared.b16 {%0,%1,%2,%3}, [%4];"
                 : "=r"(r[0]), "=r"(r[1]), "=r"(r[2]), "=r"(r[3]) : "r"(addr));
}
__device__ __forceinline__ void mma16816(float c[4], const uint32_t a[4], uint32_t b0, uint32_t b1) {
    asm volatile("mma.sync.aligned.m16n8k16.row.col.f32.bf16.bf16.f32 "
                 "{%0,%1,%2,%3}, {%4,%5,%6,%7}, {%8,%9}, {%0,%1,%2,%3};"
                 : "+f"(c[0]), "+f"(c[1]), "+f"(c[2]), "+f"(c[3])
                 : "r"(a[0]), "r"(a[1]), "r"(a[2]), "r"(a[3]), "r"(b0), "r"(b1));
}

// ---- fp32 -> (bf16 hi, bf16 lo) split with swizzled STS ----
__device__ __forceinline__ uint32_t bf2u(__nv_bfloat162 v) { return reinterpret_cast<uint32_t&>(v); }

__device__ __forceinline__ void split_store(char* hi, char* lo, uint32_t sw, float4 v) {
    __nv_bfloat162 h01 = __float22bfloat162_rn(make_float2(v.x, v.y));
    __nv_bfloat162 h23 = __float22bfloat162_rn(make_float2(v.z, v.w));
    float2 f01 = __bfloat1622float2(h01);
    float2 f23 = __bfloat1622float2(h23);
    __nv_bfloat162 l01 = __float22bfloat162_rn(make_float2(v.x - f01.x, v.y - f01.y));
    __nv_bfloat162 l23 = __float22bfloat162_rn(make_float2(v.z - f23.x, v.w - f23.y));
    *reinterpret_cast<uint2*>(hi + sw) = make_uint2(bf2u(h01), bf2u(h23));
    *reinterpret_cast<uint2*>(lo + sw) = make_uint2(bf2u(l01), bf2u(l23));
}

// ROWS x 64 fp32 tile -> hi/lo bf16 SW128 tiles. 16 lanes per row (coalesced 256B/row).
// rows < split come from src0, others from src1 (row - split). ld = fp32 row stride.
template <int ROWS>
__device__ __forceinline__ void load_tile(char* hi, char* lo,
                                          const float* __restrict__ src0,
                                          const float* __restrict__ src1,
                                          int split, int ld, int col0) {
#pragma unroll
    for (int it = 0; it < ROWS * 16; it += THREADS) {
        int idx = it + threadIdx.x;
        int row = idx >> 4, seg = idx & 15;
        const float* p = (row < split) ? (src0 + (size_t)row * ld)
                                       : (src1 + (size_t)(row - split) * ld);
        float4 v = *reinterpret_cast<const float4*>(p + col0 + seg * 4);
        uint32_t sw = swz((uint32_t)row * 128u + (uint32_t)seg * 8u);
        split_store(hi, lo, sw, v);
    }
}

// 3-pass (hi*hi, hi*lo, lo*hi) mma over one 64-elem K chunk.
// Warp tile 64x64 at (wm*64, wn*64) within the 128x256 CTA tile.
__device__ __forceinline__ void compute_chunk(uint32_t sb, int wm, int wn, int lane,
                                              float acc[4][8][4]) {
    const uint32_t abase[3] = {sb + OFF_AH, sb + OFF_AH, sb + OFF_AL};
    const uint32_t bbase[3] = {sb + OFF_BH, sb + OFF_BL, sb + OFF_BH};
#pragma unroll
    for (int p = 0; p < 3; p++) {
        uint32_t Ab = abase[p], Bb = bbase[p];
#pragma unroll
        for (int k = 0; k < 4; k++) {
            uint32_t kb = (uint32_t)k * 32u + (uint32_t)(lane >> 4) * 16u;
            uint32_t a[4][4], b[4][4];
#pragma unroll
            for (int i = 0; i < 4; i++) {
                uint32_t row = (uint32_t)(wm * 64 + i * 16 + (lane & 15));
                ldsm4(Ab + swz(row * 128u + kb), a[i]);
            }
#pragma unroll
            for (int j = 0; j < 4; j++) {
                uint32_t row = (uint32_t)(wn * 64 + j * 16 + (lane & 15));
                ldsm4(Bb + swz(row * 128u + kb), b[j]);
            }
#pragma unroll
            for (int i = 0; i < 4; i++)
#pragma unroll
                for (int j = 0; j < 4; j++) {
                    mma16816(acc[i][j * 2],     a[i], b[j][0], b[j][2]);  // n lo8
                    mma16816(acc[i][j * 2 + 1], a[i], b[j][1], b[j][3]);  // n hi8
                }
        }
    }
}

// ================= GEMM1: h = SwiGLU(x @ w12^T) =================
// grid (32 m-tiles, 11 h-col tiles of 128, 8 experts).
// B tile = [128 gate rows ; 128 up rows] for the same 128 h columns.
__global__ void __launch_bounds__(THREADS, 1)
gemm1_kernel(const float* __restrict__ x, const float* __restrict__ w12,
             const int* __restrict__ starts) {
    extern __shared__ char smem[];
    uint32_t sb = smem_u32(smem);
    int tid = threadIdx.x, lane = tid & 31, wid = tid >> 5;
    int wm = wid & 1, wn = wid >> 1;
    int mt = blockIdx.x, nt = blockIdx.y, e = blockIdx.z;

    int m0 = starts[e] + mt * TILE_M;
    const float* A  = x + (size_t)m0 * D_MODEL;
    const float* Bg = w12 + ((size_t)e * TWO_H + (size_t)nt * 128) * D_MODEL;
    const float* Bu = Bg + (size_t)HIDDEN * D_MODEL;

    float acc[4][8][4];
#pragma unroll
    for (int i = 0; i < 4; i++)
#pragma unroll
        for (int j = 0; j < 8; j++)
#pragma unroll
            for (int r = 0; r < 4; r++) acc[i][j][r] = 0.0f;

    const int NC = D_MODEL / KC;  // 8
    for (int c = 0; c < NC; c++) {
        __syncthreads();
        load_tile<TILE_M>(smem + OFF_AH, smem + OFF_AL, A, A, TILE_M, D_MODEL, c * KC);
        load_tile<TILE_NB>(smem + OFF_BH, smem + OFF_BL, Bg, Bu, 128, D_MODEL, c * KC);
        __syncthreads();
        compute_chunk(sb, wm, wn, lane, acc);
    }

    // ---- epilogue: stage fp32 tile, SwiGLU, write h ----
    __syncthreads();
    float* tile = reinterpret_cast<float*>(smem);  // [128][256]
#pragma unroll
    for (int i = 0; i < 4; i++) {
        int r0 = wm * 64 + i * 16 + (lane >> 2);
#pragma unroll
        for (int j = 0; j < 8; j++) {
            int col = wn * 64 + j * 8 + (lane & 3) * 2;
            tile[r0 * 256 + col]       = acc[i][j][0];
            tile[r0 * 256 + col + 1]   = acc[i][j][1];
            tile[(r0 + 8) * 256 + col]     = acc[i][j][2];
            tile[(r0 + 8) * 256 + col + 1] = acc[i][j][3];
        }
    }
    __syncthreads();
    for (int idx = tid; idx < 128 * 128; idx += THREADS) {
        int m = idx >> 7, j = idx & 127;
        float g = tile[m * 256 + j];
        float u = tile[m * 256 + 128 + j];
        g_h[(size_t)(m0 + m) * HIDDEN + (size_t)nt * 128 + j] = g * u / (1.0f + __expf(-g));
    }
}

// ================= GEMM2: out = h @ w3^T =================
// grid (32 m-tiles, 2 n-tiles of 256, 8 experts). K = 1408 -> 22 chunks.
__global__ void __launch_bounds__(THREADS, 1)
gemm2_kernel(const float* __restrict__ w3, const int* __restrict__ starts,
             float* __restrict__ out) {
    extern __shared__ char smem[];
    uint32_t sb = smem_u32(smem);
    int tid = threadIdx.x, lane = tid & 31, wid = tid >> 5;
    int wm = wid & 1, wn = wid >> 1;
    int mt = blockIdx.x, nt = blockIdx.y, e = blockIdx.z;

    int m0 = starts[e] + mt * TILE_M;
    const float* A = g_h + (size_t)m0 * HIDDEN;
    const float* B = w3 + ((size_t)e * D_MODEL + (size_t)nt * TILE_NB) * HIDDEN;

    float acc[4][8][4];
#pragma unroll
    for (int i = 0; i < 4; i++)
#pragma unroll
        for (int j = 0; j < 8; j++)
#pragma unroll
            for (int r = 0; r < 4; r++) acc[i][j][r] = 0.0f;

    const int NC = HIDDEN / KC;  // 22
    for (int c = 0; c < NC; c++) {
        __syncthreads();
        load_tile<TILE_M>(smem + OFF_AH, smem + OFF_AL, A, A, TILE_M, HIDDEN, c * KC);
        load_tile<TILE_NB>(smem + OFF_BH, smem + OFF_BL, B, B, TILE_NB, HIDDEN, c * KC);
        __syncthreads();
        compute_chunk(sb, wm, wn, lane, acc);
    }

    // ---- epilogue: direct fp32 stores ----
#pragma unroll
    for (int i = 0; i < 4; i++) {
        int row = m0 + wm * 64 + i * 16 + (lane >> 2);
#pragma unroll
        for (int j = 0; j < 8; j++) {
            int col = nt * TILE_NB + wn * 64 + j * 8 + (lane & 3) * 2;
            *reinterpret_cast<float2*>(out + (size_t)row * D_MODEL + col) =
                make_float2(acc[i][j][0], acc[i][j][1]);
            *reinterpret_cast<float2*>(out + (size_t)(row + 8) * D_MODEL + col) =
                make_float2(acc[i][j][2], acc[i][j][3]);
        }
    }
}

extern "C" void kernel_launch(void* const* d_in, const int* in_sizes, int n_in,
                              void* d_out, int out_size) {
    (void)in_sizes; (void)n_in; (void)out_size;
    const float* x      = (const float*)d_in[0];
    const float* w12    = (const float*)d_in[1];
    const float* w3     = (const float*)d_in[2];
    const int*   starts = (const int*)d_in[3];
    float* out = (float*)d_out;

    cudaFuncSetAttribute(gemm1_kernel, cudaFuncAttributeMaxDynamicSharedMemorySize, SMEM_G1);
    cudaFuncSetAttribute(gemm2_kernel, cudaFuncAttributeMaxDynamicSharedMemorySize, SMEM_MAIN);

    dim3 g1(32, HIDDEN / 128, 8);    // (32, 11, 8)
    dim3 g2(32, D_MODEL / TILE_NB, 8);  // (32, 2, 8)
    gemm1_kernel<<<g1, THREADS, SMEM_G1>>>(x, w12, starts);
    gemm2_kernel<<<g2, THREADS, SMEM_MAIN>>>(w3, starts, out);
}